// round 3
// baseline (speedup 1.0000x reference)
#include <cuda_runtime.h>
#include <math.h>

#define DIMN 768
#define NBATCH 16
#define SEQ 1024
#define MTOT (NBATCH * SEQ)

// Tiling constants: 128x128 tile, k-step 8, 8x8 per thread, 256 threads.
constexpr int BM = 128, BN = 128, BKT = 8, TM = 8, TN = 8;

// Scratch layout (floats):
//   Q, KA, KB, VA, VB, H : 6 * 16384*768 = 75,497,472
//   SA, SB               : 2 * 16*1024*1024 = 33,554,432
// total = 109,051,904 floats = 436 MB
__device__ float g_scratch[109051904];

// ---------------------------------------------------------------------------
// Generic NT GEMM:  C[M,N] = scale * (A[M,K] @ B[N,K]^T) + (bias[N] if hasBias)
// A,B row-major with inner dim K (both K-contiguous). Batched via strides and
// blockIdx.z. M implied by gridDim.y * BM. C row stride = N.
// ---------------------------------------------------------------------------
__global__ void __launch_bounds__(256, 2)
gemm_nt(const float* __restrict__ A, const float* __restrict__ B,
        const float* __restrict__ bias, float* __restrict__ C,
        int N, int K,
        size_t sA, size_t sB, size_t sC, float scale, int hasBias)
{
    A += (size_t)blockIdx.z * sA;
    B += (size_t)blockIdx.z * sB;
    C += (size_t)blockIdx.z * sC;

    const int bm = blockIdx.y * BM;
    const int bn = blockIdx.x * BN;

    __shared__ float As[2][BKT][BM];
    __shared__ float Bs[2][BKT][BN];

    const int tid  = threadIdx.x;
    const int lrow = tid >> 1;          // 0..127
    const int lk   = (tid & 1) << 2;    // 0 or 4

    const float* Ap = A + (size_t)(bm + lrow) * K + lk;
    const float* Bp = B + (size_t)(bn + lrow) * K + lk;

    const int tr = (tid >> 4) * TM;     // 0..120
    const int tc = (tid & 15) * TN;     // 0..120

    float acc[TM][TN] = {};

    float4 a4 = *(const float4*)Ap;
    float4 b4 = *(const float4*)Bp;
    As[0][lk + 0][lrow] = a4.x; As[0][lk + 1][lrow] = a4.y;
    As[0][lk + 2][lrow] = a4.z; As[0][lk + 3][lrow] = a4.w;
    Bs[0][lk + 0][lrow] = b4.x; Bs[0][lk + 1][lrow] = b4.y;
    Bs[0][lk + 2][lrow] = b4.z; Bs[0][lk + 3][lrow] = b4.w;
    __syncthreads();

    const int nt = K / BKT;
    int buf = 0;
    for (int t = 0; t < nt; ++t) {
        if (t + 1 < nt) {
            a4 = *(const float4*)(Ap + (size_t)(t + 1) * BKT);
            b4 = *(const float4*)(Bp + (size_t)(t + 1) * BKT);
        }
#pragma unroll
        for (int kk = 0; kk < BKT; ++kk) {
            float4 af0 = *(const float4*)&As[buf][kk][tr];
            float4 af1 = *(const float4*)&As[buf][kk][tr + 4];
            float4 bf0 = *(const float4*)&Bs[buf][kk][tc];
            float4 bf1 = *(const float4*)&Bs[buf][kk][tc + 4];
            float ar[8] = {af0.x, af0.y, af0.z, af0.w, af1.x, af1.y, af1.z, af1.w};
            float br[8] = {bf0.x, bf0.y, bf0.z, bf0.w, bf1.x, bf1.y, bf1.z, bf1.w};
#pragma unroll
            for (int i = 0; i < TM; i++)
#pragma unroll
                for (int j = 0; j < TN; j++)
                    acc[i][j] = fmaf(ar[i], br[j], acc[i][j]);
        }
        if (t + 1 < nt) {
            const int nb = buf ^ 1;
            As[nb][lk + 0][lrow] = a4.x; As[nb][lk + 1][lrow] = a4.y;
            As[nb][lk + 2][lrow] = a4.z; As[nb][lk + 3][lrow] = a4.w;
            Bs[nb][lk + 0][lrow] = b4.x; Bs[nb][lk + 1][lrow] = b4.y;
            Bs[nb][lk + 2][lrow] = b4.z; Bs[nb][lk + 3][lrow] = b4.w;
            __syncthreads();
            buf = nb;
        }
    }

    float bv[TN];
#pragma unroll
    for (int j = 0; j < TN; j++)
        bv[j] = hasBias ? bias[bn + tc + j] : 0.0f;

#pragma unroll
    for (int i = 0; i < TM; i++) {
        float* Crow = C + (size_t)(bm + tr + i) * N + bn + tc;
#pragma unroll
        for (int j = 0; j < TN; j += 4) {
            float4 o;
            o.x = fmaf(scale, acc[i][j + 0], bv[j + 0]);
            o.y = fmaf(scale, acc[i][j + 1], bv[j + 1]);
            o.z = fmaf(scale, acc[i][j + 2], bv[j + 2]);
            o.w = fmaf(scale, acc[i][j + 3], bv[j + 3]);
            *(float4*)(Crow + j) = o;
        }
    }
}

// ---------------------------------------------------------------------------
// Fused dual PV (NN GEMM):
//   out[q,d] = sum_k PA[q,k]*VA[k,d] + sum_k PB[q,k]*VB[k,d] + xC[q,d]
// Per batch (blockIdx.z). P: [SEQ,SEQ] row-major, V: [SEQ,DIMN] row-major.
// ---------------------------------------------------------------------------
__global__ void __launch_bounds__(256, 2)
attn_pv(const float* __restrict__ PA, const float* __restrict__ VA,
        const float* __restrict__ PB, const float* __restrict__ VB,
        const float* __restrict__ xC, float* __restrict__ Cout)
{
    const int z = blockIdx.z;
    const float* Pm[2] = {PA + (size_t)z * SEQ * SEQ, PB + (size_t)z * SEQ * SEQ};
    const float* Vm[2] = {VA + (size_t)z * SEQ * DIMN, VB + (size_t)z * SEQ * DIMN};
    xC   += (size_t)z * SEQ * DIMN;
    Cout += (size_t)z * SEQ * DIMN;

    const int bm = blockIdx.y * BM;
    const int bn = blockIdx.x * BN;

    __shared__ float As[2][BKT][BM];
    __shared__ float Bs[2][BKT][BN];

    const int tid  = threadIdx.x;
    const int lrow = tid >> 1;          // A-load: row in P tile
    const int lk   = (tid & 1) << 2;
    const int bkr  = tid >> 5;          // B-load: k row 0..7
    const int bnc  = (tid & 31) << 2;   // B-load: n chunk 0..124

    const int tr = (tid >> 4) * TM;
    const int tc = (tid & 15) * TN;

    float acc[TM][TN] = {};

    for (int pair = 0; pair < 2; ++pair) {
        const float* P = Pm[pair];
        const float* V = Vm[pair];
        const float* Ap = P + (size_t)(bm + lrow) * SEQ + lk;
        const float* Bp = V + (size_t)bkr * DIMN + bn + bnc;

        float4 a4 = *(const float4*)Ap;
        float4 b4 = *(const float4*)Bp;
        __syncthreads();  // previous pair's last compute must finish before overwrite
        As[0][lk + 0][lrow] = a4.x; As[0][lk + 1][lrow] = a4.y;
        As[0][lk + 2][lrow] = a4.z; As[0][lk + 3][lrow] = a4.w;
        *(float4*)&Bs[0][bkr][bnc] = b4;
        __syncthreads();

        const int nt = SEQ / BKT;  // 128
        int buf = 0;
        for (int t = 0; t < nt; ++t) {
            if (t + 1 < nt) {
                a4 = *(const float4*)(Ap + (size_t)(t + 1) * BKT);
                b4 = *(const float4*)(Bp + (size_t)(t + 1) * BKT * DIMN);
            }
#pragma unroll
            for (int kk = 0; kk < BKT; ++kk) {
                float4 af0 = *(const float4*)&As[buf][kk][tr];
                float4 af1 = *(const float4*)&As[buf][kk][tr + 4];
                float4 bf0 = *(const float4*)&Bs[buf][kk][tc];
                float4 bf1 = *(const float4*)&Bs[buf][kk][tc + 4];
                float ar[8] = {af0.x, af0.y, af0.z, af0.w, af1.x, af1.y, af1.z, af1.w};
                float br[8] = {bf0.x, bf0.y, bf0.z, bf0.w, bf1.x, bf1.y, bf1.z, bf1.w};
#pragma unroll
                for (int i = 0; i < TM; i++)
#pragma unroll
                    for (int j = 0; j < TN; j++)
                        acc[i][j] = fmaf(ar[i], br[j], acc[i][j]);
            }
            if (t + 1 < nt) {
                const int nb = buf ^ 1;
                As[nb][lk + 0][lrow] = a4.x; As[nb][lk + 1][lrow] = a4.y;
                As[nb][lk + 2][lrow] = a4.z; As[nb][lk + 3][lrow] = a4.w;
                *(float4*)&Bs[nb][bkr][bnc] = b4;
                __syncthreads();
                buf = nb;
            }
        }
    }

#pragma unroll
    for (int i = 0; i < TM; i++) {
        const float* xrow = xC + (size_t)(bm + tr + i) * DIMN + bn + tc;
        float* orow = Cout + (size_t)(bm + tr + i) * DIMN + bn + tc;
#pragma unroll
        for (int j = 0; j < TN; j += 4) {
            float4 x4 = *(const float4*)(xrow + j);
            float4 o;
            o.x = acc[i][j + 0] + x4.x;
            o.y = acc[i][j + 1] + x4.y;
            o.z = acc[i][j + 2] + x4.z;
            o.w = acc[i][j + 3] + x4.w;
            *(float4*)(orow + j) = o;
        }
    }
}

// ---------------------------------------------------------------------------
// Row softmax, in-place. grid = (NBATCH*SEQ rows, 2 matrices), 256 threads.
// ---------------------------------------------------------------------------
__global__ void softmax_rows(float* __restrict__ SA, float* __restrict__ SB)
{
    float* Sm = blockIdx.y ? SB : SA;
    float* row = Sm + (size_t)blockIdx.x * SEQ;
    const int tid = threadIdx.x;
    const unsigned FULL = 0xffffffffu;
    __shared__ float red[8];

    float v[4];
#pragma unroll
    for (int i = 0; i < 4; i++) v[i] = row[tid + (i << 8)];

    float m = fmaxf(fmaxf(v[0], v[1]), fmaxf(v[2], v[3]));
#pragma unroll
    for (int o = 16; o; o >>= 1) m = fmaxf(m, __shfl_xor_sync(FULL, m, o));
    if ((tid & 31) == 0) red[tid >> 5] = m;
    __syncthreads();
    float bm = red[0];
#pragma unroll
    for (int i = 1; i < 8; i++) bm = fmaxf(bm, red[i]);

    float s = 0.0f;
#pragma unroll
    for (int i = 0; i < 4; i++) { v[i] = __expf(v[i] - bm); s += v[i]; }
#pragma unroll
    for (int o = 16; o; o >>= 1) s += __shfl_xor_sync(FULL, s, o);
    __syncthreads();
    if ((tid & 31) == 0) red[tid >> 5] = s;
    __syncthreads();
    float bs = 0.0f;
#pragma unroll
    for (int i = 0; i < 8; i++) bs += red[i];

    const float inv = 1.0f / bs;
#pragma unroll
    for (int i = 0; i < 4; i++) row[tid + (i << 8)] = v[i] * inv;
}

// ---------------------------------------------------------------------------
// In-place LayerNorm over rows of 768. grid = MTOT rows, 256 threads.
// ---------------------------------------------------------------------------
__global__ void layernorm_inplace(float* __restrict__ H,
                                  const float* __restrict__ gamma,
                                  const float* __restrict__ beta)
{
    float* row = H + (size_t)blockIdx.x * DIMN;
    const int tid = threadIdx.x;
    const unsigned FULL = 0xffffffffu;
    __shared__ float red[8];

    float v[3];
#pragma unroll
    for (int i = 0; i < 3; i++) v[i] = row[tid + (i << 8)];

    float s = v[0] + v[1] + v[2];
#pragma unroll
    for (int o = 16; o; o >>= 1) s += __shfl_xor_sync(FULL, s, o);
    if ((tid & 31) == 0) red[tid >> 5] = s;
    __syncthreads();
    float tot = 0.0f;
#pragma unroll
    for (int i = 0; i < 8; i++) tot += red[i];
    const float mu = tot * (1.0f / (float)DIMN);

    float d0 = v[0] - mu, d1 = v[1] - mu, d2 = v[2] - mu;
    float sq = d0 * d0 + d1 * d1 + d2 * d2;
#pragma unroll
    for (int o = 16; o; o >>= 1) sq += __shfl_xor_sync(FULL, sq, o);
    __syncthreads();
    if ((tid & 31) == 0) red[tid >> 5] = sq;
    __syncthreads();
    float tot2 = 0.0f;
#pragma unroll
    for (int i = 0; i < 8; i++) tot2 += red[i];
    const float var = tot2 * (1.0f / (float)DIMN);
    const float inv = rsqrtf(var + 1e-5f);

#pragma unroll
    for (int i = 0; i < 3; i++) {
        const int c = tid + (i << 8);
        row[c] = (v[i] - mu) * inv * gamma[c] + beta[c];
    }
}

// ---------------------------------------------------------------------------
extern "C" void kernel_launch(void* const* d_in, const int* in_sizes, int n_in,
                              void* d_out, int out_size)
{
    (void)in_sizes; (void)n_in; (void)out_size;

    const float* xA    = (const float*)d_in[0];
    const float* xB    = (const float*)d_in[1];
    const float* xC    = (const float*)d_in[2];
    const float* Wq    = (const float*)d_in[3];
    const float* bq    = (const float*)d_in[4];
    const float* Wk    = (const float*)d_in[5];
    const float* bk    = (const float*)d_in[6];
    const float* Wv    = (const float*)d_in[7];
    const float* bv    = (const float*)d_in[8];
    const float* gamma = (const float*)d_in[9];
    const float* beta  = (const float*)d_in[10];
    const float* Wfc   = (const float*)d_in[11];
    const float* bfc   = (const float*)d_in[12];
    float* out = (float*)d_out;

    float* scratch = nullptr;
    cudaGetSymbolAddress((void**)&scratch, g_scratch);

    const size_t P = (size_t)MTOT * DIMN;        // 12,582,912
    float* Q  = scratch;
    float* KA = scratch + 1 * P;
    float* KB = scratch + 2 * P;
    float* VA = scratch + 3 * P;
    float* VB = scratch + 4 * P;
    float* H  = scratch + 5 * P;
    float* SA = scratch + 6 * P;
    float* SB = SA + (size_t)NBATCH * SEQ * SEQ;

    dim3 blk(256);
    dim3 gproj(DIMN / BN, MTOT / BM, 1);         // (6,128,1)

    // Projections (C = X @ W^T + b)
    gemm_nt<<<gproj, blk>>>(xC, Wq, bq, Q,  DIMN, DIMN, 0, 0, 0, 1.0f, 1);
    gemm_nt<<<gproj, blk>>>(xA, Wk, bk, KA, DIMN, DIMN, 0, 0, 0, 1.0f, 1);
    gemm_nt<<<gproj, blk>>>(xB, Wk, bk, KB, DIMN, DIMN, 0, 0, 0, 1.0f, 1);
    gemm_nt<<<gproj, blk>>>(xA, Wv, bv, VA, DIMN, DIMN, 0, 0, 0, 1.0f, 1);
    gemm_nt<<<gproj, blk>>>(xB, Wv, bv, VB, DIMN, DIMN, 0, 0, 0, 1.0f, 1);

    // Batched attention scores: S = scale * (Q @ K^T)
    const float sc = 1.0f / sqrtf((float)DIMN);
    dim3 gsc(SEQ / BN, SEQ / BM, NBATCH);        // (8,8,16)
    gemm_nt<<<gsc, blk>>>(Q, KA, nullptr, SA, SEQ, DIMN,
                          (size_t)SEQ * DIMN, (size_t)SEQ * DIMN,
                          (size_t)SEQ * SEQ, sc, 0);
    gemm_nt<<<gsc, blk>>>(Q, KB, nullptr, SB, SEQ, DIMN,
                          (size_t)SEQ * DIMN, (size_t)SEQ * DIMN,
                          (size_t)SEQ * SEQ, sc, 0);

    // Row softmax, in place
    softmax_rows<<<dim3(NBATCH * SEQ, 2), blk>>>(SA, SB);

    // interp_A + interp_B + x_C -> H
    attn_pv<<<dim3(DIMN / BN, SEQ / BM, NBATCH), blk>>>(SA, VA, SB, VB, xC, H);

    // LayerNorm in place
    layernorm_inplace<<<MTOT, blk>>>(H, gamma, beta);

    // Final FC -> d_out
    gemm_nt<<<gproj, blk>>>(H, Wfc, bfc, out, DIMN, DIMN, 0, 0, 0, 1.0f, 1);
}

// round 7
// speedup vs baseline: 1.6991x; 1.6991x over previous
#include <cuda_runtime.h>
#include <cuda_fp16.h>
#include <cstdint>
#include <cstring>
#include <math.h>

#define DIMN 768
#define NBATCH 16
#define SEQ 1024
#define MTOT (NBATCH * SEQ)

// ---------------- GEMM tile config ----------------
constexpr int BM = 128, BN = 128, BK = 32;      // BK in fp16 elements
constexpr int NTH = 256;                        // 8 warps: 2(M) x 4(N), warp tile 64x32
constexpr int SP = 40;                          // padded SMEM row stride (halfs) -> 80B
constexpr int MAT_BYTES = 128 * SP * 2;         // 10240 per matrix (hi or lo, A or B)
constexpr int STAGE = 4 * MAT_BYTES;            // Ahi,Alo,Bhi,Blo = 40960
constexpr int DSMEM = 2 * STAGE;                // 81920 double buffered

// ---------------- scratch ----------------
#define E_X 12582912ll
#define E_W 589824ll
#define E_S 16777216ll
// fp16 pool: 16*E_X + 8*E_W + 4*E_S ; f32 pool: 2*E_S (Hf reuses SA)
__device__ __align__(256) __half g_h16[273154048ll];
__device__ __align__(256) float g_f32[33554432ll];

// ---------------- helpers ----------------
__device__ __forceinline__ uint32_t smem_u32(const void* p) {
    uint32_t a;
    asm("{ .reg .u64 t; cvta.to.shared.u64 t, %1; cvt.u32.u64 %0, t; }" : "=r"(a) : "l"(p));
    return a;
}
__device__ __forceinline__ void cp16(uint32_t dst, const void* src) {
    asm volatile("cp.async.cg.shared.global [%0], [%1], 16;" :: "r"(dst), "l"(src) : "memory");
}
__device__ __forceinline__ void cp_commit() { asm volatile("cp.async.commit_group;" ::: "memory"); }
template <int N> __device__ __forceinline__ void cp_wait() {
    asm volatile("cp.async.wait_group %0;" :: "n"(N) : "memory");
}
__device__ __forceinline__ void ldsm4(uint32_t* r, uint32_t addr) {
    asm volatile("ldmatrix.sync.aligned.m8n8.x4.shared.b16 {%0,%1,%2,%3}, [%4];"
                 : "=r"(r[0]), "=r"(r[1]), "=r"(r[2]), "=r"(r[3]) : "r"(addr));
}
__device__ __forceinline__ void mma16816(float* d, const uint32_t* a, uint32_t b0, uint32_t b1) {
    asm volatile(
        "mma.sync.aligned.m16n8k16.row.col.f32.f16.f16.f32 "
        "{%0,%1,%2,%3}, {%4,%5,%6,%7}, {%8,%9}, {%0,%1,%2,%3};"
        : "+f"(d[0]), "+f"(d[1]), "+f"(d[2]), "+f"(d[3])
        : "r"(a[0]), "r"(a[1]), "r"(a[2]), "r"(a[3]), "r"(b0), "r"(b1));
}

// ---------------- generic split-fp16 HMMA GEMM ----------------
// C[m,n] = scale * sum_k A[m,k]*B[n,k]  (+bias[n]) (+resid[m,n])
// A,B as (hi,lo) fp16 pairs, K-major. nSeg=2 chains two (A,B) pairs over the
// K loop (fused dual PV). Output: fp32 and/or split-fp16 (optionally transposed).
struct GP {
    const __half *Ah0, *Al0, *Bh0, *Bl0;
    const __half *Ah1, *Al1, *Bh1, *Bl1;
    long long zA, zB, zC, zR;     // batch strides (elements)
    int sA, sB, N;                // row strides (elements), C row stride
    int ntSeg, nSeg;
    float scale;
    const float* bias;
    const float* resid;
    float* Cf;
    __half *Chi, *Clo;
    int trans;                    // transposed split store (V^T)
};

__global__ void __launch_bounds__(NTH) gemm_hmma(GP p)
{
    extern __shared__ unsigned char dsm_raw[];
    const uint32_t sbase = smem_u32(dsm_raw);

    const int tid = threadIdx.x;
    const int wid = tid >> 5;
    const int lane = tid & 31;
    const int wm = wid >> 2;            // 0..1
    const int wn = wid & 3;             // 0..3
    const int z = blockIdx.z;
    const int bm = blockIdx.y * BM;
    const int bn = blockIdx.x * BN;
    const int NT = p.ntSeg * p.nSeg;

    float acc[4][4][4];
#pragma unroll
    for (int i = 0; i < 4; i++)
#pragma unroll
        for (int j = 0; j < 4; j++)
#pragma unroll
            for (int q = 0; q < 4; q++) acc[i][j][q] = 0.0f;

    auto load_stage = [&](int t, int s) {
        const int seg = (t >= p.ntSeg) ? 1 : 0;
        const int kt = t - seg * p.ntSeg;
        const __half* Ah = (seg ? p.Ah1 : p.Ah0) + (long long)z * p.zA + (long long)kt * BK;
        const __half* Al = (seg ? p.Al1 : p.Al0) + (long long)z * p.zA + (long long)kt * BK;
        const __half* Bh = (seg ? p.Bh1 : p.Bh0) + (long long)z * p.zB + (long long)kt * BK;
        const __half* Bl = (seg ? p.Bl1 : p.Bl0) + (long long)z * p.zB + (long long)kt * BK;
        const uint32_t base = sbase + s * STAGE;
#pragma unroll
        for (int i = 0; i < 2; i++) {            // 512 (row,chunk) tasks / 256 thr
            const int idx = tid + i * NTH;
            const int row = idx >> 2, ch = idx & 3;
            const uint32_t so = base + row * (SP * 2) + ch * 16;
            const long long ga = (long long)(bm + row) * p.sA + ch * 8;
            const long long gb = (long long)(bn + row) * p.sB + ch * 8;
            cp16(so,                 Ah + ga);
            cp16(so + MAT_BYTES,     Al + ga);
            cp16(so + 2 * MAT_BYTES, Bh + gb);
            cp16(so + 3 * MAT_BYTES, Bl + gb);
        }
        cp_commit();
    };

    load_stage(0, 0);

    for (int t = 0; t < NT; t++) {
        const int s = t & 1;
        if (t + 1 < NT) { load_stage(t + 1, s ^ 1); cp_wait<1>(); }
        else           { cp_wait<0>(); }
        __syncthreads();

        const uint32_t bA = sbase + s * STAGE;
        const uint32_t bAl = bA + MAT_BYTES;
        const uint32_t bB = bA + 2 * MAT_BYTES;
        const uint32_t bBl = bA + 3 * MAT_BYTES;

#pragma unroll
        for (int k16 = 0; k16 < 2; k16++) {
            const uint32_t koff = (uint32_t)(k16 << 5);   // 32B = 16 halfs
            // A fragment addresses (row-major 16x16 via ldmatrix.x4)
            const uint32_t arow = (uint32_t)(wm * 64 + (lane & 15));
            const uint32_t aoff = arow * (SP * 2) + ((lane >> 4) << 4) + koff;
            // B fragment addresses (n-major rows, k-contiguous)
            const int q = lane >> 3, r = lane & 7;
            const uint32_t brow = (uint32_t)(wn * 32 + ((q >> 1) << 3) + r);
            const uint32_t boff = brow * (SP * 2) + ((q & 1) << 4) + koff;

            uint32_t ah[4][4], al[4][4], bh[2][4], bl[2][4];
#pragma unroll
            for (int mt = 0; mt < 4; mt++) ldsm4(ah[mt], bA + aoff + mt * 16 * (SP * 2));
#pragma unroll
            for (int nt = 0; nt < 2; nt++) ldsm4(bh[nt], bB + boff + nt * 16 * (SP * 2));
#pragma unroll
            for (int mt = 0; mt < 4; mt++) ldsm4(al[mt], bAl + aoff + mt * 16 * (SP * 2));
#pragma unroll
            for (int nt = 0; nt < 2; nt++) ldsm4(bl[nt], bBl + boff + nt * 16 * (SP * 2));

#pragma unroll
            for (int mt = 0; mt < 4; mt++)
#pragma unroll
                for (int ng = 0; ng < 4; ng++) {
                    const int g2 = ng >> 1, gi = (ng & 1) * 2;
                    mma16816(acc[mt][ng], ah[mt], bh[g2][gi], bh[g2][gi + 1]); // hi*hi
                    mma16816(acc[mt][ng], ah[mt], bl[g2][gi], bl[g2][gi + 1]); // hi*lo
                    mma16816(acc[mt][ng], al[mt], bh[g2][gi], bh[g2][gi + 1]); // lo*hi
                }
        }
        __syncthreads();   // protect buf s before load t+2 overwrites it
    }

    // ---------------- epilogue ----------------
#pragma unroll
    for (int mt = 0; mt < 4; mt++) {
#pragma unroll
        for (int ng = 0; ng < 4; ng++) {
            const int r0 = bm + wm * 64 + mt * 16 + (lane >> 2);
            const int c0 = bn + wn * 32 + ng * 8 + (lane & 3) * 2;
            float v0 = acc[mt][ng][0] * p.scale;
            float v1 = acc[mt][ng][1] * p.scale;
            float v2 = acc[mt][ng][2] * p.scale;
            float v3 = acc[mt][ng][3] * p.scale;
            if (p.bias) {
                const float b0 = __ldg(p.bias + c0), b1 = __ldg(p.bias + c0 + 1);
                v0 += b0; v1 += b1; v2 += b0; v3 += b1;
            }
            if (p.resid) {
                const float* rp = p.resid + (long long)z * p.zR;
                float2 x0 = *(const float2*)(rp + (long long)r0 * p.N + c0);
                float2 x1 = *(const float2*)(rp + (long long)(r0 + 8) * p.N + c0);
                v0 += x0.x; v1 += x0.y; v2 += x1.x; v3 += x1.y;
            }
            if (p.Cf) {
                float* cf = p.Cf + (long long)z * p.zC;
                *(float2*)(cf + (long long)r0 * p.N + c0) = make_float2(v0, v1);
                *(float2*)(cf + (long long)(r0 + 8) * p.N + c0) = make_float2(v2, v3);
            }
            if (p.Chi) {
                __half h0 = __float2half_rn(v0), h1 = __float2half_rn(v1);
                __half h2 = __float2half_rn(v2), h3 = __float2half_rn(v3);
                __half l0 = __float2half_rn(v0 - __half2float(h0));
                __half l1 = __float2half_rn(v1 - __half2float(h1));
                __half l2 = __float2half_rn(v2 - __half2float(h2));
                __half l3 = __float2half_rn(v3 - __half2float(h3));
                if (!p.trans) {
                    __half* ch = p.Chi + (long long)z * p.zC;
                    __half* cl = p.Clo + (long long)z * p.zC;
                    *(__half2*)(ch + (long long)r0 * p.N + c0) = __halves2half2(h0, h1);
                    *(__half2*)(ch + (long long)(r0 + 8) * p.N + c0) = __halves2half2(h2, h3);
                    *(__half2*)(cl + (long long)r0 * p.N + c0) = __halves2half2(l0, l1);
                    *(__half2*)(cl + (long long)(r0 + 8) * p.N + c0) = __halves2half2(l2, l3);
                } else {
                    // V^T: value at (token=m, dim=c) stored at [b][c][tok]
                    const int b0i = r0 >> 10, k0 = r0 & 1023;
                    const int b1i = (r0 + 8) >> 10, k1 = (r0 + 8) & 1023;
                    const long long vb0 = (long long)b0i * (DIMN * SEQ);
                    const long long vb1 = (long long)b1i * (DIMN * SEQ);
                    p.Chi[vb0 + (long long)c0 * SEQ + k0] = h0;
                    p.Chi[vb0 + (long long)(c0 + 1) * SEQ + k0] = h1;
                    p.Chi[vb1 + (long long)c0 * SEQ + k1] = h2;
                    p.Chi[vb1 + (long long)(c0 + 1) * SEQ + k1] = h3;
                    p.Clo[vb0 + (long long)c0 * SEQ + k0] = l0;
                    p.Clo[vb0 + (long long)(c0 + 1) * SEQ + k0] = l1;
                    p.Clo[vb1 + (long long)c0 * SEQ + k1] = l2;
                    p.Clo[vb1 + (long long)(c0 + 1) * SEQ + k1] = l3;
                }
            }
        }
    }
}

// ---------------- elementwise kernels ----------------
__global__ void split_kernel(const float* __restrict__ x, __half* __restrict__ hi,
                             __half* __restrict__ lo, long long n)
{
    long long i = ((long long)blockIdx.x * blockDim.x + threadIdx.x) * 4;
    if (i >= n) return;
    float4 v = *(const float4*)(x + i);
    float a[4] = {v.x, v.y, v.z, v.w};
    __half2 h[2], l[2];
#pragma unroll
    for (int q = 0; q < 2; q++) {
        __half h0 = __float2half_rn(a[2 * q]);
        __half h1 = __float2half_rn(a[2 * q + 1]);
        h[q] = __halves2half2(h0, h1);
        l[q] = __halves2half2(__float2half_rn(a[2 * q] - __half2float(h0)),
                              __float2half_rn(a[2 * q + 1] - __half2float(h1)));
    }
    *(uint2*)(hi + i) = *(uint2*)h;
    *(uint2*)(lo + i) = *(uint2*)l;
}

__global__ void softmax_split(const float* __restrict__ S, __half* __restrict__ Ph,
                              __half* __restrict__ Pl)
{
    const float* row = S + (long long)blockIdx.x * SEQ;
    __half* ph = Ph + (long long)blockIdx.x * SEQ;
    __half* pl = Pl + (long long)blockIdx.x * SEQ;
    const int tid = threadIdx.x;
    const unsigned FULL = 0xffffffffu;
    __shared__ float red[8];

    float v[4];
#pragma unroll
    for (int i = 0; i < 4; i++) v[i] = row[tid + (i << 8)];
    float m = fmaxf(fmaxf(v[0], v[1]), fmaxf(v[2], v[3]));
#pragma unroll
    for (int o = 16; o; o >>= 1) m = fmaxf(m, __shfl_xor_sync(FULL, m, o));
    if ((tid & 31) == 0) red[tid >> 5] = m;
    __syncthreads();
    float bm = red[0];
#pragma unroll
    for (int i = 1; i < 8; i++) bm = fmaxf(bm, red[i]);
    float s = 0.0f;
#pragma unroll
    for (int i = 0; i < 4; i++) { v[i] = __expf(v[i] - bm); s += v[i]; }
#pragma unroll
    for (int o = 16; o; o >>= 1) s += __shfl_xor_sync(FULL, s, o);
    __syncthreads();
    if ((tid & 31) == 0) red[tid >> 5] = s;
    __syncthreads();
    float bs = 0.0f;
#pragma unroll
    for (int i = 0; i < 8; i++) bs += red[i];
    const float inv = 1.0f / bs;
#pragma unroll
    for (int i = 0; i < 4; i++) {
        const int c = tid + (i << 8);
        float pv = v[i] * inv;
        __half h = __float2half_rn(pv);
        ph[c] = h;
        pl[c] = __float2half_rn(pv - __half2float(h));
    }
}

__global__ void layernorm_split(const float* __restrict__ H, const float* __restrict__ gamma,
                                const float* __restrict__ beta,
                                __half* __restrict__ Hh, __half* __restrict__ Hl)
{
    const float* row = H + (long long)blockIdx.x * DIMN;
    __half* oh = Hh + (long long)blockIdx.x * DIMN;
    __half* ol = Hl + (long long)blockIdx.x * DIMN;
    const int tid = threadIdx.x;
    const unsigned FULL = 0xffffffffu;
    __shared__ float red[8];

    float v[3];
#pragma unroll
    for (int i = 0; i < 3; i++) v[i] = row[tid + (i << 8)];
    float s = v[0] + v[1] + v[2];
#pragma unroll
    for (int o = 16; o; o >>= 1) s += __shfl_xor_sync(FULL, s, o);
    if ((tid & 31) == 0) red[tid >> 5] = s;
    __syncthreads();
    float tot = 0.0f;
#pragma unroll
    for (int i = 0; i < 8; i++) tot += red[i];
    const float mu = tot * (1.0f / (float)DIMN);
    float d0 = v[0] - mu, d1 = v[1] - mu, d2 = v[2] - mu;
    float sq = d0 * d0 + d1 * d1 + d2 * d2;
#pragma unroll
    for (int o = 16; o; o >>= 1) sq += __shfl_xor_sync(FULL, sq, o);
    __syncthreads();
    if ((tid & 31) == 0) red[tid >> 5] = sq;
    __syncthreads();
    float tot2 = 0.0f;
#pragma unroll
    for (int i = 0; i < 8; i++) tot2 += red[i];
    const float inv = rsqrtf(tot2 * (1.0f / (float)DIMN) + 1e-5f);
#pragma unroll
    for (int i = 0; i < 3; i++) {
        const int c = tid + (i << 8);
        float o = (v[i] - mu) * inv * gamma[c] + beta[c];
        __half h = __float2half_rn(o);
        oh[c] = h;
        ol[c] = __float2half_rn(o - __half2float(h));
    }
}

// ---------------- host ----------------
static GP make_gp() { GP p; memset(&p, 0, sizeof(p)); p.scale = 1.0f; p.nSeg = 1; return p; }

extern "C" void kernel_launch(void* const* d_in, const int* in_sizes, int n_in,
                              void* d_out, int out_size)
{
    (void)in_sizes; (void)n_in; (void)out_size;
    const float* xA = (const float*)d_in[0];
    const float* xB = (const float*)d_in[1];
    const float* xC = (const float*)d_in[2];
    const float* Wq = (const float*)d_in[3];
    const float* bq = (const float*)d_in[4];
    const float* Wk = (const float*)d_in[5];
    const float* bk = (const float*)d_in[6];
    const float* Wv = (const float*)d_in[7];
    const float* bv = (const float*)d_in[8];
    const float* gamma = (const float*)d_in[9];
    const float* beta = (const float*)d_in[10];
    const float* Wfc = (const float*)d_in[11];
    const float* bfc = (const float*)d_in[12];
    float* out = (float*)d_out;

    __half* hp = nullptr;
    float* fp = nullptr;
    cudaGetSymbolAddress((void**)&hp, g_h16);
    cudaGetSymbolAddress((void**)&fp, g_f32);

    long long o = 0;
    auto take = [&](long long n) { __half* r = hp + o; o += n; return r; };
    __half *xAh = take(E_X), *xAl = take(E_X), *xBh = take(E_X), *xBl = take(E_X);
    __half *xCh = take(E_X), *xCl = take(E_X);
    __half *Wqh = take(E_W), *Wql = take(E_W), *Wkh = take(E_W), *Wkl = take(E_W);
    __half *Wvh = take(E_W), *Wvl = take(E_W), *Wfh = take(E_W), *Wfl = take(E_W);
    __half *Qh = take(E_X), *Ql = take(E_X);
    __half *KAh = take(E_X), *KAl = take(E_X), *KBh = take(E_X), *KBl = take(E_X);
    __half *VTAh = take(E_X), *VTAl = take(E_X), *VTBh = take(E_X), *VTBl = take(E_X);
    __half *PAh = take(E_S), *PAl = take(E_S), *PBh = take(E_S), *PBl = take(E_S);
    __half *Hh = xAh, *Hl = xAl;          // xA split dead after V_A projection
    float* SAf = fp;
    float* SBf = fp + E_S;
    float* Hf = SAf;                      // SA dead after softmax

    cudaFuncSetAttribute(gemm_hmma, cudaFuncAttributeMaxDynamicSharedMemorySize, DSMEM);

    // 1) split fp32 -> (hi,lo) fp16
    split_kernel<<<(int)(E_X / 4 / 256), 256>>>(xA, xAh, xAl, E_X);
    split_kernel<<<(int)(E_X / 4 / 256), 256>>>(xB, xBh, xBl, E_X);
    split_kernel<<<(int)(E_X / 4 / 256), 256>>>(xC, xCh, xCl, E_X);
    split_kernel<<<(int)(E_W / 4 / 256), 256>>>(Wq, Wqh, Wql, E_W);
    split_kernel<<<(int)(E_W / 4 / 256), 256>>>(Wk, Wkh, Wkl, E_W);
    split_kernel<<<(int)(E_W / 4 / 256), 256>>>(Wv, Wvh, Wvl, E_W);
    split_kernel<<<(int)(E_W / 4 / 256), 256>>>(Wfc, Wfh, Wfl, E_W);

    const dim3 blk(NTH);
    const dim3 gproj(DIMN / BN, MTOT / BM, 1);   // (6,128,1)

    // 2) projections  C = X @ W^T + b  -> split fp16 (V transposed per batch)
    auto proj = [&](const __half* ah, const __half* al, const __half* wh, const __half* wl,
                    const float* bias, __half* ch, __half* cl, int trans) {
        GP p = make_gp();
        p.Ah0 = p.Ah1 = ah; p.Al0 = p.Al1 = al;
        p.Bh0 = p.Bh1 = wh; p.Bl0 = p.Bl1 = wl;
        p.sA = DIMN; p.sB = DIMN; p.N = DIMN;
        p.ntSeg = DIMN / BK;
        p.bias = bias; p.Chi = ch; p.Clo = cl; p.trans = trans;
        gemm_hmma<<<gproj, blk, DSMEM>>>(p);
    };
    proj(xCh, xCl, Wqh, Wql, bq, Qh, Ql, 0);
    proj(xBh, xBl, Wkh, Wkl, bk, KBh, KBl, 0);
    proj(xBh, xBl, Wvh, Wvl, bv, VTBh, VTBl, 1);
    proj(xAh, xAl, Wkh, Wkl, bk, KAh, KAl, 0);
    proj(xAh, xAl, Wvh, Wvl, bv, VTAh, VTAl, 1); // xA split dead after this

    // 3) scores  S = scale * Q @ K^T  (fp32, batched)
    const float sc = 1.0f / sqrtf((float)DIMN);
    auto scores = [&](const __half* kh, const __half* kl, float* Sf) {
        GP p = make_gp();
        p.Ah0 = p.Ah1 = Qh; p.Al0 = p.Al1 = Ql;
        p.Bh0 = p.Bh1 = kh; p.Bl0 = p.Bl1 = kl;
        p.sA = DIMN; p.sB = DIMN; p.N = SEQ;
        p.zA = (long long)SEQ * DIMN; p.zB = (long long)SEQ * DIMN; p.zC = (long long)SEQ * SEQ;
        p.ntSeg = DIMN / BK;
        p.scale = sc; p.Cf = Sf;
        gemm_hmma<<<dim3(SEQ / BN, SEQ / BM, NBATCH), blk, DSMEM>>>(p);
    };
    scores(KAh, KAl, SAf);
    scores(KBh, KBl, SBf);

    // 4) softmax -> split fp16 P  (SA consumed before Hf reuses its space)
    softmax_split<<<MTOT, blk>>>(SAf, PAh, PAl);
    softmax_split<<<MTOT, blk>>>(SBf, PBh, PBl);

    // 5) fused dual PV + residual:  H = PA@VA + PB@VB + xC  (fp32)
    {
        GP p = make_gp();
        p.Ah0 = PAh; p.Al0 = PAl; p.Bh0 = VTAh; p.Bl0 = VTAl;
        p.Ah1 = PBh; p.Al1 = PBl; p.Bh1 = VTBh; p.Bl1 = VTBl;
        p.sA = SEQ; p.sB = SEQ; p.N = DIMN;
        p.zA = (long long)SEQ * SEQ; p.zB = (long long)DIMN * SEQ;
        p.zC = (long long)SEQ * DIMN; p.zR = (long long)SEQ * DIMN;
        p.ntSeg = SEQ / BK; p.nSeg = 2;
        p.resid = xC; p.Cf = Hf;
        gemm_hmma<<<dim3(DIMN / BN, SEQ / BM, NBATCH), blk, DSMEM>>>(p);
    }

    // 6) layernorm -> split fp16 H
    layernorm_split<<<MTOT, blk>>>(Hf, gamma, beta, Hh, Hl);

    // 7) FC -> d_out (fp32 + bias)
    {
        GP p = make_gp();
        p.Ah0 = p.Ah1 = Hh; p.Al0 = p.Al1 = Hl;
        p.Bh0 = p.Bh1 = Wfh; p.Bl0 = p.Bl1 = Wfl;
        p.sA = DIMN; p.sB = DIMN; p.N = DIMN;
        p.ntSeg = DIMN / BK;
        p.bias = bfc; p.Cf = out;
        gemm_hmma<<<gproj, blk, DSMEM>>>(p);
    }
}

// round 8
// speedup vs baseline: 2.3277x; 1.3699x over previous
#include <cuda_runtime.h>
#include <cuda_fp16.h>
#include <cstdint>
#include <cstring>
#include <math.h>

#define DIMN 768
#define NBATCH 16
#define SEQ 1024
#define MTOT (NBATCH * SEQ)

// ---------------- GEMM tile config ----------------
constexpr int BM = 128, BN = 128, BK = 32;      // BK in fp16 elements
constexpr int NTH = 256;                        // 8 warps: 2(M) x 4(N), warp tile 64x32
constexpr int SP = 40;                          // padded SMEM row stride (halfs) -> 80B
constexpr int MAT_BYTES = 128 * SP * 2;         // 10240 per matrix (hi or lo, A or B)
constexpr int STAGE = 4 * MAT_BYTES;            // Ahi,Alo,Bhi,Blo = 40960
constexpr int NSTAGE = 3;
constexpr int DSMEM = NSTAGE * STAGE;           // 122880

// ---------------- scratch ----------------
#define E_X 12582912ll
#define E_W 589824ll
#define E_S 16777216ll
__device__ __align__(256) __half g_h16[273154048ll];
__device__ __align__(256) float g_f32[33554432ll];

// ---------------- helpers ----------------
__device__ __forceinline__ uint32_t smem_u32(const void* p) {
    uint32_t a;
    asm("{ .reg .u64 t; cvta.to.shared.u64 t, %1; cvt.u32.u64 %0, t; }" : "=r"(a) : "l"(p));
    return a;
}
__device__ __forceinline__ void cp16(uint32_t dst, const void* src) {
    asm volatile("cp.async.cg.shared.global [%0], [%1], 16;" :: "r"(dst), "l"(src) : "memory");
}
__device__ __forceinline__ void cp_commit() { asm volatile("cp.async.commit_group;" ::: "memory"); }
template <int N> __device__ __forceinline__ void cp_wait() {
    asm volatile("cp.async.wait_group %0;" :: "n"(N) : "memory");
}
__device__ __forceinline__ void ldsm4(uint32_t* r, uint32_t addr) {
    asm volatile("ldmatrix.sync.aligned.m8n8.x4.shared.b16 {%0,%1,%2,%3}, [%4];"
                 : "=r"(r[0]), "=r"(r[1]), "=r"(r[2]), "=r"(r[3]) : "r"(addr));
}
__device__ __forceinline__ void mma16816(float* d, const uint32_t* a, uint32_t b0, uint32_t b1) {
    asm volatile(
        "mma.sync.aligned.m16n8k16.row.col.f32.f16.f16.f32 "
        "{%0,%1,%2,%3}, {%4,%5,%6,%7}, {%8,%9}, {%0,%1,%2,%3};"
        : "+f"(d[0]), "+f"(d[1]), "+f"(d[2]), "+f"(d[3])
        : "r"(a[0]), "r"(a[1]), "r"(a[2]), "r"(a[3]), "r"(b0), "r"(b1));
}

// ---------------- multi-op split-fp16 HMMA GEMM ----------------
// Per op: C = scale*(A@B^T) (+bias) (+resid). Ops indexed either by
// blockIdx.z/zBat (fused independent GEMMs) or by K-segment (nSeg=2: dual PV).
struct GP {
    const __half *Ah[5], *Al[5], *Bh[5], *Bl[5];
    const float* bias[5];
    float* Cf[5];
    __half *Chi[5], *Clo[5];
    int trans[5];
    const float* resid;
    long long zA, zB, zC, zR;     // per-batch strides (elements)
    int sA, sB, N;                // row strides, C row stride
    int ntSeg, nSeg, zBat;
    float scale;
};

__global__ void __launch_bounds__(NTH) gemm_hmma(GP p)
{
    extern __shared__ unsigned char dsm_raw[];
    const uint32_t sbase = smem_u32(dsm_raw);

    const int tid = threadIdx.x;
    const int wid = tid >> 5;
    const int lane = tid & 31;
    const int wm = wid >> 2;
    const int wn = wid & 3;
    const int zOp = blockIdx.z / p.zBat;
    const int zb  = blockIdx.z % p.zBat;
    const int bm = blockIdx.y * BM;
    const int bn = blockIdx.x * BN;
    const int NT = p.ntSeg * p.nSeg;

    float acc[4][4][4];
#pragma unroll
    for (int i = 0; i < 4; i++)
#pragma unroll
        for (int j = 0; j < 4; j++)
#pragma unroll
            for (int q = 0; q < 4; q++) acc[i][j][q] = 0.0f;

    auto load_stage = [&](int t, int s) {
        const int seg = (p.nSeg == 2 && t >= p.ntSeg) ? 1 : 0;
        const int oi = (p.nSeg == 2) ? seg : zOp;
        const int kt = t - seg * p.ntSeg;
        const __half* Ah = p.Ah[oi] + (long long)zb * p.zA + (long long)kt * BK;
        const __half* Al = p.Al[oi] + (long long)zb * p.zA + (long long)kt * BK;
        const __half* Bh = p.Bh[oi] + (long long)zb * p.zB + (long long)kt * BK;
        const __half* Bl = p.Bl[oi] + (long long)zb * p.zB + (long long)kt * BK;
        const uint32_t base = sbase + s * STAGE;
#pragma unroll
        for (int i = 0; i < 2; i++) {            // 512 (row,chunk) tasks / 256 thr
            const int idx = tid + i * NTH;
            const int row = idx >> 2, ch = idx & 3;
            const uint32_t so = base + row * (SP * 2) + ch * 16;
            const long long ga = (long long)(bm + row) * p.sA + ch * 8;
            const long long gb = (long long)(bn + row) * p.sB + ch * 8;
            cp16(so,                 Ah + ga);
            cp16(so + MAT_BYTES,     Al + ga);
            cp16(so + 2 * MAT_BYTES, Bh + gb);
            cp16(so + 3 * MAT_BYTES, Bl + gb);
        }
        cp_commit();
    };

    load_stage(0, 0);
    load_stage(1, 1);

    // hoisted fragment base offsets (byte offsets within a matrix)
    const uint32_t SP2 = SP * 2;
    const uint32_t aoff0 = (uint32_t)(wm * 64 + (lane & 15)) * SP2 + (((uint32_t)lane >> 4) << 4);
    const int q = lane >> 3, r = lane & 7;
    const uint32_t boff0 = (uint32_t)(wn * 32 + ((q >> 1) << 3) + r) * SP2 + (((uint32_t)q & 1) << 4);

    for (int t = 0; t < NT; t++) {
        if (t + 1 < NT) cp_wait<1>(); else cp_wait<0>();
        __syncthreads();                          // stage t ready; compute t-1 done by all
        if (t + 2 < NT) load_stage(t + 2, (t + 2) % NSTAGE);

        const uint32_t bA  = sbase + (t % NSTAGE) * STAGE;
        const uint32_t bAl = bA + MAT_BYTES;
        const uint32_t bB  = bA + 2 * MAT_BYTES;
        const uint32_t bBl = bA + 3 * MAT_BYTES;

#pragma unroll
        for (int k16 = 0; k16 < 2; k16++) {
            const uint32_t koff = (uint32_t)(k16 << 5);
            uint32_t ah[4][4], al[4][4], bh[2][4], bl[2][4];
#pragma unroll
            for (int mt = 0; mt < 4; mt++) ldsm4(ah[mt], bA + aoff0 + koff + mt * 16 * SP2);
#pragma unroll
            for (int nt = 0; nt < 2; nt++) ldsm4(bh[nt], bB + boff0 + koff + nt * 16 * SP2);
            // term 0: hi*hi (overlaps with lo-fragment loads below)
#pragma unroll
            for (int mt = 0; mt < 4; mt++)
#pragma unroll
                for (int ng = 0; ng < 4; ng++) {
                    const int g2 = ng >> 1, gi = (ng & 1) * 2;
                    mma16816(acc[mt][ng], ah[mt], bh[g2][gi], bh[g2][gi + 1]);
                }
#pragma unroll
            for (int mt = 0; mt < 4; mt++) ldsm4(al[mt], bAl + aoff0 + koff + mt * 16 * SP2);
#pragma unroll
            for (int nt = 0; nt < 2; nt++) ldsm4(bl[nt], bBl + boff0 + koff + nt * 16 * SP2);
            // term 1: hi*lo
#pragma unroll
            for (int mt = 0; mt < 4; mt++)
#pragma unroll
                for (int ng = 0; ng < 4; ng++) {
                    const int g2 = ng >> 1, gi = (ng & 1) * 2;
                    mma16816(acc[mt][ng], ah[mt], bl[g2][gi], bl[g2][gi + 1]);
                }
            // term 2: lo*hi
#pragma unroll
            for (int mt = 0; mt < 4; mt++)
#pragma unroll
                for (int ng = 0; ng < 4; ng++) {
                    const int g2 = ng >> 1, gi = (ng & 1) * 2;
                    mma16816(acc[mt][ng], al[mt], bh[g2][gi], bh[g2][gi + 1]);
                }
        }
    }

    // ---------------- epilogue (per-op outputs) ----------------
    const int eo = zOp;
#pragma unroll
    for (int mt = 0; mt < 4; mt++) {
#pragma unroll
        for (int ng = 0; ng < 4; ng++) {
            const int r0 = bm + wm * 64 + mt * 16 + (lane >> 2);
            const int c0 = bn + wn * 32 + ng * 8 + (lane & 3) * 2;
            float v0 = acc[mt][ng][0] * p.scale;
            float v1 = acc[mt][ng][1] * p.scale;
            float v2 = acc[mt][ng][2] * p.scale;
            float v3 = acc[mt][ng][3] * p.scale;
            if (p.bias[eo]) {
                const float b0 = __ldg(p.bias[eo] + c0), b1 = __ldg(p.bias[eo] + c0 + 1);
                v0 += b0; v1 += b1; v2 += b0; v3 += b1;
            }
            if (p.resid) {
                const float* rp = p.resid + (long long)zb * p.zR;
                float2 x0 = *(const float2*)(rp + (long long)r0 * p.N + c0);
                float2 x1 = *(const float2*)(rp + (long long)(r0 + 8) * p.N + c0);
                v0 += x0.x; v1 += x0.y; v2 += x1.x; v3 += x1.y;
            }
            if (p.Cf[eo]) {
                float* cf = p.Cf[eo] + (long long)zb * p.zC;
                *(float2*)(cf + (long long)r0 * p.N + c0) = make_float2(v0, v1);
                *(float2*)(cf + (long long)(r0 + 8) * p.N + c0) = make_float2(v2, v3);
            }
            if (p.Chi[eo]) {
                __half h0 = __float2half_rn(v0), h1 = __float2half_rn(v1);
                __half h2 = __float2half_rn(v2), h3 = __float2half_rn(v3);
                __half l0 = __float2half_rn(v0 - __half2float(h0));
                __half l1 = __float2half_rn(v1 - __half2float(h1));
                __half l2 = __float2half_rn(v2 - __half2float(h2));
                __half l3 = __float2half_rn(v3 - __half2float(h3));
                if (!p.trans[eo]) {
                    __half* ch = p.Chi[eo] + (long long)zb * p.zC;
                    __half* cl = p.Clo[eo] + (long long)zb * p.zC;
                    *(__half2*)(ch + (long long)r0 * p.N + c0) = __halves2half2(h0, h1);
                    *(__half2*)(ch + (long long)(r0 + 8) * p.N + c0) = __halves2half2(h2, h3);
                    *(__half2*)(cl + (long long)r0 * p.N + c0) = __halves2half2(l0, l1);
                    *(__half2*)(cl + (long long)(r0 + 8) * p.N + c0) = __halves2half2(l2, l3);
                } else {
                    const int b0i = r0 >> 10, k0 = r0 & 1023;
                    const int b1i = (r0 + 8) >> 10, k1 = (r0 + 8) & 1023;
                    const long long vb0 = (long long)b0i * (DIMN * SEQ);
                    const long long vb1 = (long long)b1i * (DIMN * SEQ);
                    p.Chi[eo][vb0 + (long long)c0 * SEQ + k0] = h0;
                    p.Chi[eo][vb0 + (long long)(c0 + 1) * SEQ + k0] = h1;
                    p.Chi[eo][vb1 + (long long)c0 * SEQ + k1] = h2;
                    p.Chi[eo][vb1 + (long long)(c0 + 1) * SEQ + k1] = h3;
                    p.Clo[eo][vb0 + (long long)c0 * SEQ + k0] = l0;
                    p.Clo[eo][vb0 + (long long)(c0 + 1) * SEQ + k0] = l1;
                    p.Clo[eo][vb1 + (long long)c0 * SEQ + k1] = l2;
                    p.Clo[eo][vb1 + (long long)(c0 + 1) * SEQ + k1] = l3;
                }
            }
        }
    }
}

// ---------------- fused split kernel (all 7 tensors, one launch) ----------------
constexpr int BLKX = (int)(E_X / 1024);  // 12288 blocks per big tensor
constexpr int BLKW = (int)(E_W / 1024);  // 576 blocks per weight
struct SplitP { const float* src[7]; __half* hi[7]; __half* lo[7]; };

__global__ void split_all(SplitP sp)
{
    int bid = blockIdx.x, seg, off;
    if (bid < 3 * BLKX) { seg = bid / BLKX; off = bid % BLKX; }
    else { int b2 = bid - 3 * BLKX; seg = 3 + b2 / BLKW; off = b2 % BLKW; }
    const long long i = ((long long)off * 256 + threadIdx.x) * 4;
    float4 v = *(const float4*)(sp.src[seg] + i);
    float a[4] = {v.x, v.y, v.z, v.w};
    __half2 h[2], l[2];
#pragma unroll
    for (int t = 0; t < 2; t++) {
        __half h0 = __float2half_rn(a[2 * t]);
        __half h1 = __float2half_rn(a[2 * t + 1]);
        h[t] = __halves2half2(h0, h1);
        l[t] = __halves2half2(__float2half_rn(a[2 * t] - __half2float(h0)),
                              __float2half_rn(a[2 * t + 1] - __half2float(h1)));
    }
    *(uint2*)(sp.hi[seg] + i) = *(uint2*)h;
    *(uint2*)(sp.lo[seg] + i) = *(uint2*)l;
}

// ---------------- softmax / layernorm ----------------
__global__ void softmax_split(const float* __restrict__ S, __half* __restrict__ Ph,
                              __half* __restrict__ Pl)
{
    const float* row = S + (long long)blockIdx.x * SEQ;
    __half* ph = Ph + (long long)blockIdx.x * SEQ;
    __half* pl = Pl + (long long)blockIdx.x * SEQ;
    const int tid = threadIdx.x;
    const unsigned FULL = 0xffffffffu;
    __shared__ float red[8];

    float v[4];
#pragma unroll
    for (int i = 0; i < 4; i++) v[i] = row[tid + (i << 8)];
    float m = fmaxf(fmaxf(v[0], v[1]), fmaxf(v[2], v[3]));
#pragma unroll
    for (int o = 16; o; o >>= 1) m = fmaxf(m, __shfl_xor_sync(FULL, m, o));
    if ((tid & 31) == 0) red[tid >> 5] = m;
    __syncthreads();
    float bm = red[0];
#pragma unroll
    for (int i = 1; i < 8; i++) bm = fmaxf(bm, red[i]);
    float s = 0.0f;
#pragma unroll
    for (int i = 0; i < 4; i++) { v[i] = __expf(v[i] - bm); s += v[i]; }
#pragma unroll
    for (int o = 16; o; o >>= 1) s += __shfl_xor_sync(FULL, s, o);
    __syncthreads();
    if ((tid & 31) == 0) red[tid >> 5] = s;
    __syncthreads();
    float bs = 0.0f;
#pragma unroll
    for (int i = 0; i < 8; i++) bs += red[i];
    const float inv = 1.0f / bs;
#pragma unroll
    for (int i = 0; i < 4; i++) {
        const int c = tid + (i << 8);
        float pv = v[i] * inv;
        __half h = __float2half_rn(pv);
        ph[c] = h;
        pl[c] = __float2half_rn(pv - __half2float(h));
    }
}

__global__ void layernorm_split(const float* __restrict__ H, const float* __restrict__ gamma,
                                const float* __restrict__ beta,
                                __half* __restrict__ Hh, __half* __restrict__ Hl)
{
    const float* row = H + (long long)blockIdx.x * DIMN;
    __half* oh = Hh + (long long)blockIdx.x * DIMN;
    __half* ol = Hl + (long long)blockIdx.x * DIMN;
    const int tid = threadIdx.x;
    const unsigned FULL = 0xffffffffu;
    __shared__ float red[8];

    float v[3];
#pragma unroll
    for (int i = 0; i < 3; i++) v[i] = row[tid + (i << 8)];
    float s = v[0] + v[1] + v[2];
#pragma unroll
    for (int o = 16; o; o >>= 1) s += __shfl_xor_sync(FULL, s, o);
    if ((tid & 31) == 0) red[tid >> 5] = s;
    __syncthreads();
    float tot = 0.0f;
#pragma unroll
    for (int i = 0; i < 8; i++) tot += red[i];
    const float mu = tot * (1.0f / (float)DIMN);
    float d0 = v[0] - mu, d1 = v[1] - mu, d2 = v[2] - mu;
    float sq = d0 * d0 + d1 * d1 + d2 * d2;
#pragma unroll
    for (int o = 16; o; o >>= 1) sq += __shfl_xor_sync(FULL, sq, o);
    __syncthreads();
    if ((tid & 31) == 0) red[tid >> 5] = sq;
    __syncthreads();
    float tot2 = 0.0f;
#pragma unroll
    for (int i = 0; i < 8; i++) tot2 += red[i];
    const float inv = rsqrtf(tot2 * (1.0f / (float)DIMN) + 1e-5f);
#pragma unroll
    for (int i = 0; i < 3; i++) {
        const int c = tid + (i << 8);
        float o = (v[i] - mu) * inv * gamma[c] + beta[c];
        __half h = __float2half_rn(o);
        oh[c] = h;
        ol[c] = __float2half_rn(o - __half2float(h));
    }
}

// ---------------- host ----------------
static GP make_gp() { GP p; memset(&p, 0, sizeof(p)); p.scale = 1.0f; p.nSeg = 1; p.zBat = 1; return p; }

extern "C" void kernel_launch(void* const* d_in, const int* in_sizes, int n_in,
                              void* d_out, int out_size)
{
    (void)in_sizes; (void)n_in; (void)out_size;
    const float* xA = (const float*)d_in[0];
    const float* xB = (const float*)d_in[1];
    const float* xC = (const float*)d_in[2];
    const float* Wq = (const float*)d_in[3];
    const float* bq = (const float*)d_in[4];
    const float* Wk = (const float*)d_in[5];
    const float* bk = (const float*)d_in[6];
    const float* Wv = (const float*)d_in[7];
    const float* bv = (const float*)d_in[8];
    const float* gamma = (const float*)d_in[9];
    const float* beta = (const float*)d_in[10];
    const float* Wfc = (const float*)d_in[11];
    const float* bfc = (const float*)d_in[12];
    float* out = (float*)d_out;

    __half* hpool = nullptr;
    float* fpool = nullptr;
    cudaGetSymbolAddress((void**)&hpool, g_h16);
    cudaGetSymbolAddress((void**)&fpool, g_f32);

    long long o = 0;
    auto take = [&](long long n) { __half* r = hpool + o; o += n; return r; };
    __half *xAh = take(E_X), *xAl = take(E_X), *xBh = take(E_X), *xBl = take(E_X);
    __half *xCh = take(E_X), *xCl = take(E_X);
    __half *Wqh = take(E_W), *Wql = take(E_W), *Wkh = take(E_W), *Wkl = take(E_W);
    __half *Wvh = take(E_W), *Wvl = take(E_W), *Wfh = take(E_W), *Wfl = take(E_W);
    __half *Qh = take(E_X), *Ql = take(E_X);
    __half *KAh = take(E_X), *KAl = take(E_X), *KBh = take(E_X), *KBl = take(E_X);
    __half *VTAh = take(E_X), *VTAl = take(E_X), *VTBh = take(E_X), *VTBl = take(E_X);
    __half *PAh = take(E_S), *PAl = take(E_S), *PBh = take(E_S), *PBl = take(E_S);
    __half *Hh = xAh, *Hl = xAl;          // xA split dead after projections
    float* SAf = fpool;
    float* SBf = fpool + E_S;
    float* Hf = SAf;                      // SA dead after softmax

    cudaFuncSetAttribute(gemm_hmma, cudaFuncAttributeMaxDynamicSharedMemorySize, DSMEM);

    // 1) fused split: all 7 fp32 -> (hi,lo) fp16
    {
        SplitP sp;
        sp.src[0] = xA; sp.hi[0] = xAh; sp.lo[0] = xAl;
        sp.src[1] = xB; sp.hi[1] = xBh; sp.lo[1] = xBl;
        sp.src[2] = xC; sp.hi[2] = xCh; sp.lo[2] = xCl;
        sp.src[3] = Wq; sp.hi[3] = Wqh; sp.lo[3] = Wql;
        sp.src[4] = Wk; sp.hi[4] = Wkh; sp.lo[4] = Wkl;
        sp.src[5] = Wv; sp.hi[5] = Wvh; sp.lo[5] = Wvl;
        sp.src[6] = Wfc; sp.hi[6] = Wfh; sp.lo[6] = Wfl;
        split_all<<<3 * BLKX + 4 * BLKW, 256>>>(sp);
    }

    const dim3 blk(NTH);

    // 2) fused projections: 5 ops in one launch (grid.z = op)
    {
        GP p = make_gp();
        const __half* As[5][2] = {{xCh, xCl}, {xAh, xAl}, {xAh, xAl}, {xBh, xBl}, {xBh, xBl}};
        const __half* Bs[5][2] = {{Wqh, Wql}, {Wkh, Wkl}, {Wvh, Wvl}, {Wkh, Wkl}, {Wvh, Wvl}};
        const float* bs[5] = {bq, bk, bv, bk, bv};
        __half* ch[5] = {Qh, KAh, VTAh, KBh, VTBh};
        __half* cl[5] = {Ql, KAl, VTAl, KBl, VTBl};
        const int tr[5] = {0, 0, 1, 0, 1};
        for (int i = 0; i < 5; i++) {
            p.Ah[i] = As[i][0]; p.Al[i] = As[i][1];
            p.Bh[i] = Bs[i][0]; p.Bl[i] = Bs[i][1];
            p.bias[i] = bs[i]; p.Chi[i] = ch[i]; p.Clo[i] = cl[i]; p.trans[i] = tr[i];
        }
        p.sA = DIMN; p.sB = DIMN; p.N = DIMN; p.ntSeg = DIMN / BK;
        gemm_hmma<<<dim3(DIMN / BN, MTOT / BM, 5), blk, DSMEM>>>(p);
    }

    // 3) fused scores: S = scale * Q @ K^T for both A and B (grid.z = op*16+batch)
    {
        GP p = make_gp();
        p.Ah[0] = Qh; p.Al[0] = Ql; p.Bh[0] = KAh; p.Bl[0] = KAl; p.Cf[0] = SAf;
        p.Ah[1] = Qh; p.Al[1] = Ql; p.Bh[1] = KBh; p.Bl[1] = KBl; p.Cf[1] = SBf;
        p.sA = DIMN; p.sB = DIMN; p.N = SEQ; p.ntSeg = DIMN / BK;
        p.zA = (long long)SEQ * DIMN; p.zB = (long long)SEQ * DIMN; p.zC = (long long)SEQ * SEQ;
        p.zBat = NBATCH;
        p.scale = 1.0f / sqrtf((float)DIMN);
        gemm_hmma<<<dim3(SEQ / BN, SEQ / BM, 2 * NBATCH), blk, DSMEM>>>(p);
    }

    // 4) softmax -> split fp16 P (two launches so PV is launch #6 for ncu -s 5)
    softmax_split<<<MTOT, blk>>>(SAf, PAh, PAl);
    softmax_split<<<MTOT, blk>>>(SBf, PBh, PBl);

    // 5) fused dual PV + residual:  H = PA@VA + PB@VB + xC
    {
        GP p = make_gp();
        p.Ah[0] = PAh; p.Al[0] = PAl; p.Bh[0] = VTAh; p.Bl[0] = VTAl;
        p.Ah[1] = PBh; p.Al[1] = PBl; p.Bh[1] = VTBh; p.Bl[1] = VTBl;
        p.sA = SEQ; p.sB = SEQ; p.N = DIMN;
        p.zA = (long long)SEQ * SEQ; p.zB = (long long)DIMN * SEQ;
        p.zC = (long long)SEQ * DIMN; p.zR = (long long)SEQ * DIMN;
        p.ntSeg = SEQ / BK; p.nSeg = 2; p.zBat = NBATCH;
        p.resid = xC; p.Cf[0] = Hf;
        gemm_hmma<<<dim3(DIMN / BN, SEQ / BM, NBATCH), blk, DSMEM>>>(p);
    }

    // 6) layernorm -> split fp16 H
    layernorm_split<<<MTOT, blk>>>(Hf, gamma, beta, Hh, Hl);

    // 7) FC -> d_out
    {
        GP p = make_gp();
        p.Ah[0] = Hh; p.Al[0] = Hl; p.Bh[0] = Wfh; p.Bl[0] = Wfl;
        p.sA = DIMN; p.sB = DIMN; p.N = DIMN; p.ntSeg = DIMN / BK;
        p.bias[0] = bfc; p.Cf[0] = out;
        gemm_hmma<<<dim3(DIMN / BN, MTOT / BM, 1), blk, DSMEM>>>(p);
    }
}